// round 16
// baseline (speedup 1.0000x reference)
#include <cuda_runtime.h>
#include <cuda_bf16.h>
#include <math_constants.h>

// ExactScoreNetwork: out[b,d] = sqrt(1-e_b) * sum_k p_bk * (x_bd - a_b*c_kd) / v_bkd
//   e = exp(-Beta(t)), a = sqrt(e), v = 1 + e*(s^2 - 1)
//   p_bk = softmax_k( -0.5*sum_d diff^2/v - 128*sum_d ln v + ln w_k )
//
// CTA = 64 threads (2 warps), 2 batch rows. Warp w handles K-half [w*64, w*64+64).
// The TWO ROWS are packed into f32x2 register pairs: all row-dependent math uses
// Blackwell packed fma.rn.f32x2 / mul.rn.f32x2 (FFMA2: 2 FMAs per issue slot),
// halving FMA-pipe pressure (the measured R13 bottleneck, ~85% busy).
// Shared c/u operands are duplicated into pairs via mov.b64 on the idle ALU pipe.
// Softmax rescale is a rare warp-uniform branch; warp reduction is a fused
// 2-value tree (8 shfl instead of 20).

constexpr int K_COMP = 128;
constexpr int D_DIM  = 256;
constexpr int KHALF  = K_COMP / 2;

__device__ float g_u[K_COMP * D_DIM];   // stds^2 - 1
__device__ float g_lw2[K_COMP];         // log2(weights)

typedef unsigned long long u64;

__device__ __forceinline__ float frcp(float x){ float r; asm("rcp.approx.ftz.f32 %0, %1;" : "=f"(r) : "f"(x)); return r; }
__device__ __forceinline__ float flg2(float x){ float r; asm("lg2.approx.ftz.f32 %0, %1;" : "=f"(r) : "f"(x)); return r; }
__device__ __forceinline__ float fex2(float x){ float r; asm("ex2.approx.ftz.f32 %0, %1;" : "=f"(r) : "f"(x)); return r; }

__device__ __forceinline__ u64 pack2(float lo, float hi){
    u64 r; asm("mov.b64 %0, {%1, %2};" : "=l"(r) : "r"(__float_as_uint(lo)), "r"(__float_as_uint(hi))); return r;
}
__device__ __forceinline__ void unpack2(u64 v, float& lo, float& hi){
    unsigned int a, b; asm("mov.b64 {%0, %1}, %2;" : "=r"(a), "=r"(b) : "l"(v));
    lo = __uint_as_float(a); hi = __uint_as_float(b);
}
__device__ __forceinline__ u64 fma2(u64 a, u64 b, u64 c){
    u64 r; asm("fma.rn.f32x2 %0, %1, %2, %3;" : "=l"(r) : "l"(a), "l"(b), "l"(c)); return r;
}
__device__ __forceinline__ u64 mul2(u64 a, u64 b){
    u64 r; asm("mul.rn.f32x2 %0, %1, %2;" : "=l"(r) : "l"(a), "l"(b)); return r;
}
__device__ __forceinline__ u64 add2(u64 a, u64 b){
    u64 r; asm("add.rn.f32x2 %0, %1, %2;" : "=l"(r) : "l"(a), "l"(b)); return r;
}

// accurate-ish log2: split exponent, lg2.approx on mantissa in [1,2)
__device__ __forceinline__ float log2_acc(float p){
    int b = __float_as_int(p);
    float m = __int_as_float((b & 0x007FFFFF) | 0x3F800000);
    return (float)((b >> 23) - 127) + flg2(m);
}

__global__ void prep_kernel(const float* __restrict__ stds, const float* __restrict__ weights)
{
    int i = blockIdx.x * blockDim.x + threadIdx.x;      // 0 .. K*D-1
    float s = stds[i];
    g_u[i] = fmaf(s, s, -1.0f);
    if (i < K_COMP) g_lw2[i] = log2f(weights[i]);
}

__global__ void __launch_bounds__(64)
score_kernel(const float* __restrict__ x, const float* __restrict__ t,
             const float* __restrict__ centers, float* __restrict__ out)
{
    __shared__ float s_acc[2][32][8];
    __shared__ float s_mx[2], s_den[2];

    const int lane = threadIdx.x & 31;
    const int w    = threadIdx.x >> 5;          // warp id in CTA: K-half selector
    const int b0   = blockIdx.x * 2;            // two rows per CTA

    const u64 ONE2 = pack2(1.0f, 1.0f);

    // per-row scalars (both warps compute both rows); rows packed as (row0, row1)
    float ev[2], naf[2], osc[2];
    #pragma unroll
    for (int r = 0; r < 2; r++) {
        float tt = t[b0 + r];
        float Bt = fmaf(9.95f, tt * tt, 0.1f * tt);   // Beta(t) = 0.1 t + 9.95 t^2
        float e  = expf(-Bt);                          // accurate: matters for 1-e at small t
        ev[r]  = e;
        naf[r] = -sqrtf(e);                            // -a
        osc[r] = sqrtf(fmaxf(1.0f - e, 0.0f));
    }
    const u64 e2  = pack2(ev[0],  ev[1]);
    const u64 na2 = pack2(naf[0], naf[1]);

    u64 x2[8], acc2[8];
    #pragma unroll
    for (int r = 0; r < 2; r++) {
        const float4* xp = reinterpret_cast<const float4*>(x + (size_t)(b0 + r) * D_DIM + lane * 8);
        float4 a = xp[0], b = xp[1];
        float xs[8] = {a.x,a.y,a.z,a.w,b.x,b.y,b.z,b.w};
        #pragma unroll
        for (int j = 0; j < 8; j++) {
            if (r == 0) x2[j] = pack2(xs[j], 0.0f);
            else {
                float lo, hi; unpack2(x2[j], lo, hi);
                x2[j] = pack2(lo, xs[j]);
            }
        }
    }
    #pragma unroll
    for (int j = 0; j < 8; j++) acc2[j] = 0ull;
    float mx0 = -CUDART_INF_F, mx1 = -CUDART_INF_F;    // log2-domain running max per row
    u64 den2 = 0ull;

    const int kbeg = w * KHALF;
    #pragma unroll 1
    for (int k = kbeg; k < kbeg + KHALF; k++) {
        const float4* cp = reinterpret_cast<const float4*>(centers + (size_t)k * D_DIM + lane * 8);
        const float4* up = reinterpret_cast<const float4*>(g_u     + (size_t)k * D_DIM + lane * 8);
        float4 c0 = __ldg(cp), c1 = __ldg(cp + 1);
        float4 u0 = __ldg(up), u1 = __ldg(up + 1);
        float c[8] = {c0.x,c0.y,c0.z,c0.w,c1.x,c1.y,c1.z,c1.w};
        float u[8] = {u0.x,u0.y,u0.z,u0.w,u1.x,u1.y,u1.z,u1.w};
        float lw2 = g_lw2[k];

        u64 g2[8];
        u64 q2 = 0ull, pr2 = ONE2;
        #pragma unroll
        for (int j = 0; j < 8; j++) {
            u64 ud = pack2(u[j], u[j]);               // dup on ALU pipe
            u64 cd = pack2(c[j], c[j]);
            u64 v2 = fma2(e2, ud, ONE2);              // v in [0.25, 1] per half
            float v0, v1; unpack2(v2, v0, v1);
            u64 rv2 = pack2(frcp(v0), frcp(v1));      // 2x MUFU
            u64 d2  = fma2(na2, cd, x2[j]);           // diff
            u64 gg  = mul2(d2, rv2);                  // diff / v
            q2  = fma2(d2, gg, q2);                   // sum diff^2 / v
            pr2 = mul2(pr2, v2);                      // chunk product for log-det
            g2[j] = gg;
        }
        float q0, q1, pr0, pr1;
        unpack2(q2, q0, q1);
        unpack2(pr2, pr0, pr1);
        // per-lane combined log2-domain partial: z = -0.5*log2e*q - 128*log2(prod)
        float z0 = fmaf(-0.72134752044448170f, q0, -128.0f * log2_acc(pr0));
        float z1 = fmaf(-0.72134752044448170f, q1, -128.0f * log2_acc(pr1));

        // fused 2-value tree reduction: combine rows into warp halves, reduce, broadcast
        float t0 = __shfl_xor_sync(0xffffffffu, z0, 16);
        float t1 = __shfl_xor_sync(0xffffffffu, z1, 16);
        float wv = (lane < 16) ? (z0 + t0) : (z1 + t1);
        wv += __shfl_xor_sync(0xffffffffu, wv, 8);
        wv += __shfl_xor_sync(0xffffffffu, wv, 4);
        wv += __shfl_xor_sync(0xffffffffu, wv, 2);
        wv += __shfl_xor_sync(0xffffffffu, wv, 1);
        float lp0 = __shfl_sync(0xffffffffu, wv, 0)  + lw2;
        float lp1 = __shfl_sync(0xffffffffu, wv, 16) + lw2;

        // rare warp-uniform rescale (E[#max-updates] ~ ln K)
        if (lp0 > mx0 || lp1 > mx1) {
            float nm0 = fmaxf(mx0, lp0), nm1 = fmaxf(mx1, lp1);
            u64 sc2 = pack2(fex2(mx0 - nm0), fex2(mx1 - nm1));  // ex2(-inf)=0 on first k
            den2 = mul2(den2, sc2);
            #pragma unroll
            for (int j = 0; j < 8; j++) acc2[j] = mul2(acc2[j], sc2);
            mx0 = nm0; mx1 = nm1;
        }
        u64 p2 = pack2(fex2(lp0 - mx0), fex2(lp1 - mx1));
        den2 = add2(den2, p2);
        #pragma unroll
        for (int j = 0; j < 8; j++)
            acc2[j] = fma2(p2, g2[j], acc2[j]);       // softmax-weighted grad accum
    }

    // ── merge the two K-half states ──
    // warp w merges row (rm = w); it exports its OTHER row (ro = 1-w) to smem slot w.
    const int rm = w, ro = 1 - w;
    float accs[2][8];
    #pragma unroll
    for (int j = 0; j < 8; j++) unpack2(acc2[j], accs[0][j], accs[1][j]);
    float den0, den1; unpack2(den2, den0, den1);
    float mxr[2]  = {mx0, mx1};
    float denr[2] = {den0, den1};

    #pragma unroll
    for (int j = 0; j < 8; j++) s_acc[w][lane][j] = accs[ro][j];
    if (lane == 0) { s_mx[w] = mxr[ro]; s_den[w] = denr[ro]; }
    __syncthreads();

    float omx  = s_mx[ro];                 // partner warp's state for row rm
    float oden = s_den[ro];
    float mn = fmaxf(mxr[rm], omx);
    float sa = fex2(mxr[rm] - mn);
    float sb = fex2(omx - mn);
    float dtot = fmaf(denr[rm], sa, oden * sb);
    float s = osc[rm] * frcp(dtot);

    float4 o0, o1;
    float oacc[8];
    #pragma unroll
    for (int j = 0; j < 8; j++)
        oacc[j] = fmaf(accs[rm][j], sa, s_acc[ro][lane][j] * sb) * s;
    o0.x = oacc[0]; o0.y = oacc[1]; o0.z = oacc[2]; o0.w = oacc[3];
    o1.x = oacc[4]; o1.y = oacc[5]; o1.z = oacc[6]; o1.w = oacc[7];
    float4* op = reinterpret_cast<float4*>(out + (size_t)(b0 + rm) * D_DIM + lane * 8);
    op[0] = o0; op[1] = o1;
}

extern "C" void kernel_launch(void* const* d_in, const int* in_sizes, int n_in,
                              void* d_out, int out_size)
{
    const float* x       = (const float*)d_in[0];   // [B, 256]
    const float* t       = (const float*)d_in[1];   // [B]
    const float* centers = (const float*)d_in[2];   // [128, 256]
    const float* stds    = (const float*)d_in[3];   // [128, 256]
    const float* weights = (const float*)d_in[4];   // [128]
    float* out = (float*)d_out;                      // [B, 256]

    int B = in_sizes[1];                             // t element count

    prep_kernel<<<(K_COMP * D_DIM) / 128, 128>>>(stds, weights);
    score_kernel<<<B / 2, 64>>>(x, t, centers, out);
}